// round 16
// baseline (speedup 1.0000x reference)
#include <cuda_runtime.h>
#include <cuda_fp16.h>
#include <cstdint>
#include <cstddef>

// L=28, B=2, S=1024, E=1024, H=8, D=128. M=B*S=2048. out[2,28,2,8,1024,128] f32.

__device__ __half d_X[2048 * 1024];
__device__ __half d_W[2ULL * 28 * 1024 * 1024];   // [kv][l][n][e] = W*ln_w
__device__ float  d_g[28 * 2048];
__device__ float  d_cosT[1024 * 64];
__device__ float  d_sinT[1024 * 64];

__device__ __forceinline__ uint32_t smem_u32(const void* p) {
    uint32_t a;
    asm("{ .reg .u64 t; cvta.to.shared.u64 t, %1; cvt.u32.u64 %0, t; }" : "=r"(a) : "l"(p));
    return a;
}
#define CP_ASYNC16(dst, src) asm volatile("cp.async.cg.shared.global [%0], [%1], 16;" :: "r"(dst), "l"(src))
#define CP_COMMIT() asm volatile("cp.async.commit_group;" ::: "memory")
#define CP_WAIT(n)  asm volatile("cp.async.wait_group %0;" :: "n"(n) : "memory")
#define LDSM_X4(r0, r1, r2, r3, a) asm volatile( \
    "ldmatrix.sync.aligned.m8n8.x4.shared.b16 {%0,%1,%2,%3}, [%4];" \
    : "=r"(r0), "=r"(r1), "=r"(r2), "=r"(r3) : "r"(a))
#define MMA16816(d, a, b) asm volatile( \
    "mma.sync.aligned.m16n8k16.row.col.f32.f16.f16.f32 {%0,%1,%2,%3}, {%4,%5,%6,%7}, {%8,%9}, {%0,%1,%2,%3};" \
    : "+f"((d)[0]), "+f"((d)[1]), "+f"((d)[2]), "+f"((d)[3]) \
    : "r"((a)[0]), "r"((a)[1]), "r"((a)[2]), "r"((a)[3]), "r"((b)[0]), "r"((b)[1]))

// ---------------- prepass ----------------
__global__ void prep_x(const float* __restrict__ x, const float* __restrict__ sc) {
    const int m = blockIdx.x, tid = threadIdx.x;
    const float* row = x + (size_t)m * 1024;
    float ss = 0.f;
#pragma unroll
    for (int i = 0; i < 4; ++i) {
        int e = tid + i * 256; float v = row[e]; ss += v * v;
        d_X[(size_t)m * 1024 + e] = __float2half_rn(v);
    }
#pragma unroll
    for (int o = 16; o; o >>= 1) ss += __shfl_xor_sync(~0u, ss, o);
    __shared__ float w[8];
    if ((tid & 31) == 0) w[tid >> 5] = ss;
    __syncthreads();
    if (tid == 0) { float t = 0.f; for (int i = 0; i < 8; ++i) t += w[i]; w[0] = t; }
    __syncthreads();
    const float msq = w[0] * (1.f / 1024.f);
    if (tid < 28) { float s = sc[tid]; d_g[tid * 2048 + m] = s * rsqrtf(s * s * msq + 1e-6f); }
}
__global__ void prep_w(const float* __restrict__ Wk, const float* __restrict__ Wv, const float* __restrict__ lnw) {
    const size_t i4 = (size_t)blockIdx.x * 256 + threadIdx.x;      // float4 idx, 14680064 total
    const int e4 = (int)(i4 & 255), n = (int)((i4 >> 8) & 1023);
    const int l = (int)((i4 >> 18) % 28), kv = (int)(i4 / (28u << 18));
    const float4 wv = reinterpret_cast<const float4*>(kv ? Wv : Wk)[((size_t)l << 18) + ((size_t)n << 8) + e4];
    const float4 gv = reinterpret_cast<const float4*>(lnw)[((size_t)l << 8) + e4];
    __half2 h0 = __floats2half2_rn(wv.x * gv.x, wv.y * gv.y);
    __half2 h1 = __floats2half2_rn(wv.z * gv.z, wv.w * gv.w);
    uint2 o; o.x = *(unsigned*)&h0; o.y = *(unsigned*)&h1;
    reinterpret_cast<uint2*>(d_W)[i4] = o;
}
__global__ void prep_rope() {
    const int i = blockIdx.x * 256 + threadIdx.x, s = i >> 6, j = i & 63;
    const double a = (double)s * pow(1.0e6, -(double)j / 64.0);
    d_cosT[i] = (float)cos(a); d_sinT[i] = (float)sin(a);
}

// ------- main GEMM: 128x128 tile, 4 warps (64x64 each), K-step 64, 3-stage -------
static constexpr int NST = 3;
static constexpr int RSTR = 144;                   // 128B data + 16B pad per row
static constexpr int STG = 128 * RSTR;             // 18432 B per operand stage
static constexpr int SMEM_SZ = 2 * NST * STG;      // 110592; epilogue needs 67072
static constexpr int CSTRIDE = 130;

__global__ void __launch_bounds__(128, 2)
gemm_kernel(const float* __restrict__ knw, float* __restrict__ out) {
    extern __shared__ __align__(128) char smem[];
    const uint32_t sb = smem_u32(smem);
    const int tid = threadIdx.x, lane = tid & 31, warp = tid >> 5;
    const int wm = warp >> 1, wn = warp & 1;
    const int inst = blockIdx.x >> 7, t = blockIdx.x & 127;
    const int l = inst >> 1, kv = inst & 1, mt = t >> 3, nt = t & 7;

    const __half* gA = d_X + (size_t)(mt * 128) * 1024;
    const __half* gB = d_W + ((size_t)(kv * 28 + l) * 1024 + nt * 128) * 1024;

    auto issue = [&](int stage, int kb) {
        const uint32_t aB = sb + stage * STG, bB = sb + NST * STG + stage * STG;
#pragma unroll
        for (int j = 0; j < 8; ++j) {
            const int i = tid + j * 128, row = i >> 3, q = i & 7;
            CP_ASYNC16(aB + row * RSTR + q * 16, gA + (size_t)row * 1024 + kb + q * 8);
            CP_ASYNC16(bB + row * RSTR + q * 16, gB + (size_t)row * 1024 + kb + q * 8);
        }
        CP_COMMIT();
    };

    // ldmatrix offsets (bytes within a stage); kh adds kh*32
    uint32_t aoff[4], boff[4];
#pragma unroll
    for (int mi = 0; mi < 4; ++mi)
        aoff[mi] = (wm * 64 + mi * 16 + (lane & 15)) * RSTR + (lane >> 4) * 16;
#pragma unroll
    for (int np = 0; np < 4; ++np)
        boff[np] = (wn * 64 + np * 16 + (lane >> 4) * 8 + (lane & 7)) * RSTR + ((lane >> 3) & 1) * 16;

    float acc[4][8][4] = {};

    // compute one K-64 step from stage st; LDSM interleaved with MMA
    auto compute = [&](int st) {
        const uint32_t aS = sb + st * STG, bS = sb + NST * STG + st * STG;
#pragma unroll
        for (int kh = 0; kh < 4; ++kh) {
            uint32_t a[4][4], bb[8][2];
            LDSM_X4(bb[0][0], bb[0][1], bb[1][0], bb[1][1], bS + boff[0] + kh * 32);
            LDSM_X4(bb[2][0], bb[2][1], bb[3][0], bb[3][1], bS + boff[1] + kh * 32);
            LDSM_X4(bb[4][0], bb[4][1], bb[5][0], bb[5][1], bS + boff[2] + kh * 32);
            LDSM_X4(bb[6][0], bb[6][1], bb[7][0], bb[7][1], bS + boff[3] + kh * 32);
            LDSM_X4(a[0][0], a[0][1], a[0][2], a[0][3], aS + aoff[0] + kh * 32);
            LDSM_X4(a[1][0], a[1][1], a[1][2], a[1][3], aS + aoff[1] + kh * 32);
#pragma unroll
            for (int nj = 0; nj < 8; ++nj) MMA16816(acc[0][nj], a[0], bb[nj]);
            LDSM_X4(a[2][0], a[2][1], a[2][2], a[2][3], aS + aoff[2] + kh * 32);
#pragma unroll
            for (int nj = 0; nj < 8; ++nj) MMA16816(acc[1][nj], a[1], bb[nj]);
            LDSM_X4(a[3][0], a[3][1], a[3][2], a[3][3], aS + aoff[3] + kh * 32);
#pragma unroll
            for (int nj = 0; nj < 8; ++nj) MMA16816(acc[2][nj], a[2], bb[nj]);
#pragma unroll
            for (int nj = 0; nj < 8; ++nj) MMA16816(acc[3][nj], a[3], bb[nj]);
        }
    };

    issue(0, 0); issue(1, 64);
#pragma unroll 1
    for (int kt = 0; kt < 5; ++kt) {
        const int kb = kt * 192;
        CP_WAIT(1); __syncthreads();
        compute(0);
        if (kb + 128 < 1024) issue(2, kb + 128);
        CP_WAIT(1); __syncthreads();
        compute(1);
        if (kb + 192 < 1024) issue(0, kb + 192);
        CP_WAIT(1); __syncthreads();
        compute(2);
        if (kb + 256 < 1024) issue(1, kb + 256);
    }
    CP_WAIT(0); __syncthreads();
    compute(0);   // ks = 15

    // ---- stage C through smem (stride 130 floats) ----
    __syncthreads();
    float* Cs = reinterpret_cast<float*>(smem);
    float* Rn = reinterpret_cast<float*>(smem) + 128 * CSTRIDE;
#pragma unroll
    for (int mi = 0; mi < 4; ++mi)
#pragma unroll
        for (int nj = 0; nj < 8; ++nj)
#pragma unroll
            for (int e = 0; e < 4; ++e) {
                const int r = wm * 64 + mi * 16 + (lane >> 2) + (e >> 1) * 8;
                const int c = wn * 64 + nj * 8 + (lane & 3) * 2 + (e & 1);
                Cs[r * CSTRIDE + c] = acc[mi][nj][e];
            }
    __syncthreads();

    // ---- per-row g*rn (1 thread/row, float2 reads) ----
    if (kv == 0) {
        const int row = tid;
        const float2* cp = reinterpret_cast<const float2*>(Cs + row * CSTRIDE);
        float ss = 0.f;
#pragma unroll
        for (int i = 0; i < 64; ++i) { const float2 v = cp[i]; ss += v.x * v.x + v.y * v.y; }
        const float g = d_g[l * 2048 + mt * 128 + row];
        Rn[row] = g * rsqrtf(g * g * ss * (1.f / 128.f) + 1e-6f);
        __syncthreads();
    }

    // ---- write phase: each warp owns 32 rows; lane i handles pair (2i, 2i+1) ----
    const int j0 = lane * 2;
#pragma unroll 1
    for (int ri = 0; ri < 32; ++ri) {
        const int row = warp * 32 + ri;
        const int m = mt * 128 + row, b = m >> 10, s = m & 1023;
        const size_t base = ((((size_t)((kv * 28 + l) * 2 + b)) * 8 + nt) * 1024 + s) * 128;
        const float2 lo = *reinterpret_cast<const float2*>(Cs + row * CSTRIDE + j0);
        const float2 hi = *reinterpret_cast<const float2*>(Cs + row * CSTRIDE + j0 + 64);
        float2 olo, ohi;
        if (kv == 0) {
            const float gr = Rn[row];
            const float2 kwl = *reinterpret_cast<const float2*>(knw + l * 128 + j0);
            const float2 kwh = *reinterpret_cast<const float2*>(knw + l * 128 + j0 + 64);
            const float a0 = lo.x * gr * kwl.x, a1 = lo.y * gr * kwl.y;
            const float b0 = hi.x * gr * kwh.x, b1 = hi.y * gr * kwh.y;
            const float2 cs = *reinterpret_cast<const float2*>(d_cosT + s * 64 + j0);
            const float2 sn = *reinterpret_cast<const float2*>(d_sinT + s * 64 + j0);
            olo = make_float2(a0 * cs.x - b0 * sn.x, a1 * cs.y - b1 * sn.y);
            ohi = make_float2(b0 * cs.x + a0 * sn.x, b1 * cs.y + a1 * sn.y);
        } else {
            const float g = d_g[l * 2048 + m];
            olo = make_float2(lo.x * g, lo.y * g);
            ohi = make_float2(hi.x * g, hi.y * g);
        }
        *reinterpret_cast<float2*>(out + base + j0) = olo;
        *reinterpret_cast<float2*>(out + base + 64 + j0) = ohi;
    }
}

// ---------------- host ----------------
extern "C" void kernel_launch(void* const* d_in, const int* in_sizes, int n_in,
                              void* d_out, int out_size) {
    const float* x   = (const float*)d_in[0];
    const float* sc  = (const float*)d_in[1];
    const float* lnw = (const float*)d_in[2];
    const float* Wk  = (const float*)d_in[3];
    const float* Wv  = (const float*)d_in[4];
    const float* knw = (const float*)d_in[5];
    float* out = (float*)d_out;

    cudaFuncSetAttribute(gemm_kernel, cudaFuncAttributeMaxDynamicSharedMemorySize, SMEM_SZ);

    prep_x<<<2048, 256>>>(x, sc);
    prep_w<<<57344, 256>>>(Wk, Wv, lnw);
    prep_rope<<<256, 256>>>();
    gemm_kernel<<<7168, 128, SMEM_SZ>>>(knw, out);
}

// round 17
// speedup vs baseline: 1.5556x; 1.5556x over previous
#include <cuda_runtime.h>
#include <cuda_fp16.h>
#include <cstdint>
#include <cstddef>

// L=28, B=2, S=1024, E=1024, H=8, D=128. M=B*S=2048. out[2,28,2,8,1024,128] f32.

__device__ __half d_X[2048 * 1024];
__device__ __half d_W[2ULL * 28 * 1024 * 1024];   // [kv][l][n][e] = W*ln_w
__device__ float  d_g[28 * 2048];
__device__ float  d_cosT[1024 * 64];
__device__ float  d_sinT[1024 * 64];

__device__ __forceinline__ uint32_t smem_u32(const void* p) {
    uint32_t a;
    asm("{ .reg .u64 t; cvta.to.shared.u64 t, %1; cvt.u32.u64 %0, t; }" : "=r"(a) : "l"(p));
    return a;
}
#define CP_ASYNC16(dst, src) asm volatile("cp.async.cg.shared.global [%0], [%1], 16;" :: "r"(dst), "l"(src))
#define CP_COMMIT() asm volatile("cp.async.commit_group;" ::: "memory")
#define CP_WAIT(n)  asm volatile("cp.async.wait_group %0;" :: "n"(n) : "memory")
#define LDSM_X4(r0, r1, r2, r3, a) asm volatile( \
    "ldmatrix.sync.aligned.m8n8.x4.shared.b16 {%0,%1,%2,%3}, [%4];" \
    : "=r"(r0), "=r"(r1), "=r"(r2), "=r"(r3) : "r"(a))
#define MMA16816(d, a, b) asm volatile( \
    "mma.sync.aligned.m16n8k16.row.col.f32.f16.f16.f32 {%0,%1,%2,%3}, {%4,%5,%6,%7}, {%8,%9}, {%0,%1,%2,%3};" \
    : "+f"((d)[0]), "+f"((d)[1]), "+f"((d)[2]), "+f"((d)[3]) \
    : "r"((a)[0]), "r"((a)[1]), "r"((a)[2]), "r"((a)[3]), "r"((b)[0]), "r"((b)[1]))
#define STCS2(p, v) asm volatile("st.global.cs.v2.f32 [%0], {%1, %2};" :: "l"(p), "f"((v).x), "f"((v).y) : "memory")

// ---------------- prepass ----------------
__global__ void prep_x(const float* __restrict__ x, const float* __restrict__ sc) {
    const int m = blockIdx.x, tid = threadIdx.x;
    const float* row = x + (size_t)m * 1024;
    float ss = 0.f;
#pragma unroll
    for (int i = 0; i < 4; ++i) {
        int e = tid + i * 256; float v = row[e]; ss += v * v;
        d_X[(size_t)m * 1024 + e] = __float2half_rn(v);
    }
#pragma unroll
    for (int o = 16; o; o >>= 1) ss += __shfl_xor_sync(~0u, ss, o);
    __shared__ float w[8];
    if ((tid & 31) == 0) w[tid >> 5] = ss;
    __syncthreads();
    if (tid == 0) { float t = 0.f; for (int i = 0; i < 8; ++i) t += w[i]; w[0] = t; }
    __syncthreads();
    const float msq = w[0] * (1.f / 1024.f);
    if (tid < 28) { float s = sc[tid]; d_g[tid * 2048 + m] = s * rsqrtf(s * s * msq + 1e-6f); }
}
__global__ void prep_w(const float* __restrict__ Wk, const float* __restrict__ Wv, const float* __restrict__ lnw) {
    const size_t i4 = (size_t)blockIdx.x * 256 + threadIdx.x;      // float4 idx, 14680064 total
    const int e4 = (int)(i4 & 255), n = (int)((i4 >> 8) & 1023);
    const int l = (int)((i4 >> 18) % 28), kv = (int)(i4 / (28u << 18));
    const float4 wv = reinterpret_cast<const float4*>(kv ? Wv : Wk)[((size_t)l << 18) + ((size_t)n << 8) + e4];
    const float4 gv = reinterpret_cast<const float4*>(lnw)[((size_t)l << 8) + e4];
    __half2 h0 = __floats2half2_rn(wv.x * gv.x, wv.y * gv.y);
    __half2 h1 = __floats2half2_rn(wv.z * gv.z, wv.w * gv.w);
    uint2 o; o.x = *(unsigned*)&h0; o.y = *(unsigned*)&h1;
    reinterpret_cast<uint2*>(d_W)[i4] = o;
}
__global__ void prep_rope() {
    const int i = blockIdx.x * 256 + threadIdx.x, s = i >> 6, j = i & 63;
    const double a = (double)s * pow(1.0e6, -(double)j / 64.0);
    d_cosT[i] = (float)cos(a); d_sinT[i] = (float)sin(a);
}

// ---------------- main GEMM: 128x128 tile, 8 warps (64x32), K-step 64, 3-stage ----------------
static constexpr int NST = 3;
static constexpr int RSTR = 144;                   // 128B data + 16B pad per row
static constexpr int STG = 128 * RSTR;             // 18432 B per operand stage
static constexpr int SMEM_SZ = 2 * NST * STG;      // 110592; epilogue needs 66560
static constexpr int CSTRIDE = 130;

__global__ void __launch_bounds__(256, 2)
gemm_kernel(const float* __restrict__ knw, float* __restrict__ out) {
    extern __shared__ __align__(128) char smem[];
    const uint32_t sb = smem_u32(smem);
    const int tid = threadIdx.x, lane = tid & 31, warp = tid >> 5;
    const int wm = warp >> 2, wn = warp & 3;
    const int inst = blockIdx.x >> 7, t = blockIdx.x & 127;
    const int l = inst >> 1, kv = inst & 1, mt = t >> 3, nt = t & 7;

    const __half* gA = d_X + (size_t)(mt * 128) * 1024;
    const __half* gB = d_W + ((size_t)(kv * 28 + l) * 1024 + nt * 128) * 1024;

    auto issue = [&](int stage, int kb) {
        const uint32_t aB = sb + stage * STG, bB = sb + NST * STG + stage * STG;
#pragma unroll
        for (int j = 0; j < 4; ++j) {
            const int i = tid + j * 256, row = i >> 3, q = i & 7;
            CP_ASYNC16(aB + row * RSTR + q * 16, gA + (size_t)row * 1024 + kb + q * 8);
            CP_ASYNC16(bB + row * RSTR + q * 16, gB + (size_t)row * 1024 + kb + q * 8);
        }
        CP_COMMIT();
    };

    // ldmatrix offsets (bytes within a stage); kh adds kh*32
    uint32_t aoff[4], boff[2];
#pragma unroll
    for (int mi = 0; mi < 4; ++mi)
        aoff[mi] = (wm * 64 + mi * 16 + (lane & 15)) * RSTR + (lane >> 4) * 16;
#pragma unroll
    for (int np = 0; np < 2; ++np)
        boff[np] = (wn * 32 + np * 16 + (lane >> 4) * 8 + (lane & 7)) * RSTR + ((lane >> 3) & 1) * 16;

    float acc[4][4][4] = {};

    // one K-64 step from stage st; optional next-stage issue after kh=0
    auto compute = [&](int st, bool doIssue, int ist, int ikb) {
        const uint32_t aS = sb + st * STG, bS = sb + NST * STG + st * STG;
#pragma unroll
        for (int kh = 0; kh < 4; ++kh) {
            uint32_t a[4][4], bb[4][2];
            LDSM_X4(bb[0][0], bb[0][1], bb[1][0], bb[1][1], bS + boff[0] + kh * 32);
            LDSM_X4(bb[2][0], bb[2][1], bb[3][0], bb[3][1], bS + boff[1] + kh * 32);
            LDSM_X4(a[0][0], a[0][1], a[0][2], a[0][3], aS + aoff[0] + kh * 32);
            LDSM_X4(a[1][0], a[1][1], a[1][2], a[1][3], aS + aoff[1] + kh * 32);
#pragma unroll
            for (int nj = 0; nj < 4; ++nj) MMA16816(acc[0][nj], a[0], bb[nj]);
            LDSM_X4(a[2][0], a[2][1], a[2][2], a[2][3], aS + aoff[2] + kh * 32);
#pragma unroll
            for (int nj = 0; nj < 4; ++nj) MMA16816(acc[1][nj], a[1], bb[nj]);
            LDSM_X4(a[3][0], a[3][1], a[3][2], a[3][3], aS + aoff[3] + kh * 32);
#pragma unroll
            for (int nj = 0; nj < 4; ++nj) MMA16816(acc[2][nj], a[2], bb[nj]);
#pragma unroll
            for (int nj = 0; nj < 4; ++nj) MMA16816(acc[3][nj], a[3], bb[nj]);
            if (kh == 0 && doIssue) issue(ist, ikb);
        }
    };

    issue(0, 0); issue(1, 64);
#pragma unroll 1
    for (int kt = 0; kt < 5; ++kt) {
        const int kb = kt * 192;
        CP_WAIT(1); __syncthreads();
        compute(0, kb + 128 < 1024, 2, kb + 128);
        CP_WAIT(1); __syncthreads();
        compute(1, kb + 192 < 1024, 0, kb + 192);
        CP_WAIT(1); __syncthreads();
        compute(2, kb + 256 < 1024, 1, kb + 256);
    }
    CP_WAIT(0); __syncthreads();
    compute(0, false, 0, 0);   // ks = 15

    // ---- stage C through smem (stride 130 floats) ----
    __syncthreads();
    float* Cs = reinterpret_cast<float*>(smem);
#pragma unroll
    for (int mi = 0; mi < 4; ++mi)
#pragma unroll
        for (int nj = 0; nj < 4; ++nj)
#pragma unroll
            for (int e = 0; e < 4; ++e) {
                const int r = wm * 64 + mi * 16 + (lane >> 2) + (e >> 1) * 8;
                const int c = wn * 32 + nj * 8 + (lane & 3) * 2 + (e & 1);
                Cs[r * CSTRIDE + c] = acc[mi][nj][e];
            }
    __syncthreads();

    // ---- write phase with fused K-RMSNorm: each warp owns 16 rows ----
    const int j0 = lane * 2;
#pragma unroll 1
    for (int ri = 0; ri < 16; ++ri) {
        const int row = warp * 16 + ri;
        const int m = mt * 128 + row, b = m >> 10, s = m & 1023;
        const size_t base = ((((size_t)((kv * 28 + l) * 2 + b)) * 8 + nt) * 1024 + s) * 128;
        const float2 lo = *reinterpret_cast<const float2*>(Cs + row * CSTRIDE + j0);
        const float2 hi = *reinterpret_cast<const float2*>(Cs + row * CSTRIDE + j0 + 64);
        float2 olo, ohi;
        if (kv == 0) {
            // row sum-of-squares across the warp (32 lanes x 4 values = 128)
            float ss = lo.x * lo.x + lo.y * lo.y + hi.x * hi.x + hi.y * hi.y;
#pragma unroll
            for (int o = 16; o; o >>= 1) ss += __shfl_xor_sync(~0u, ss, o);
            const float g = d_g[l * 2048 + m];
            const float gr = g * rsqrtf(g * g * ss * (1.f / 128.f) + 1e-6f);
            const float2 kwl = *reinterpret_cast<const float2*>(knw + l * 128 + j0);
            const float2 kwh = *reinterpret_cast<const float2*>(knw + l * 128 + j0 + 64);
            const float a0 = lo.x * gr * kwl.x, a1 = lo.y * gr * kwl.y;
            const float b0 = hi.x * gr * kwh.x, b1 = hi.y * gr * kwh.y;
            const float2 cs = *reinterpret_cast<const float2*>(d_cosT + s * 64 + j0);
            const float2 sn = *reinterpret_cast<const float2*>(d_sinT + s * 64 + j0);
            olo = make_float2(a0 * cs.x - b0 * sn.x, a1 * cs.y - b1 * sn.y);
            ohi = make_float2(b0 * cs.x + a0 * sn.x, b1 * cs.y + a1 * sn.y);
        } else {
            const float g = d_g[l * 2048 + m];
            olo = make_float2(lo.x * g, lo.y * g);
            ohi = make_float2(hi.x * g, hi.y * g);
        }
        STCS2(out + base + j0, olo);
        STCS2(out + base + 64 + j0, ohi);
    }
}

// ---------------- host ----------------
extern "C" void kernel_launch(void* const* d_in, const int* in_sizes, int n_in,
                              void* d_out, int out_size) {
    const float* x   = (const float*)d_in[0];
    const float* sc  = (const float*)d_in[1];
    const float* lnw = (const float*)d_in[2];
    const float* Wk  = (const float*)d_in[3];
    const float* Wv  = (const float*)d_in[4];
    const float* knw = (const float*)d_in[5];
    float* out = (float*)d_out;

    cudaFuncSetAttribute(gemm_kernel, cudaFuncAttributeMaxDynamicSharedMemorySize, SMEM_SZ);

    prep_x<<<2048, 256>>>(x, sc);
    prep_w<<<57344, 256>>>(Wk, Wv, lnw);
    prep_rope<<<256, 256>>>();
    gemm_kernel<<<7168, 256, SMEM_SZ>>>(knw, out);
}